// round 7
// baseline (speedup 1.0000x reference)
#include <cuda_runtime.h>
#include <cstdint>

#define NB   16384
#define DD   1024
#define EPSF 1e-8f
#define TILE 128
#define KCH  32
#define LDA  132   // padded smem stride (floats): conflict-free transpose stores

// ---------------- device scratch (allocation-free rule: __device__ globals) ----
__device__ float               g_xn[(size_t)NB * DD];   // 64 MB normalized X (fp32)
__device__ unsigned long long  g_best[NB];              // packed (orderable dot << 32 | j)
__device__ float               g_logs[NB];              // per-row log distance

// ---------------- helpers ------------------------------------------------------
__device__ __forceinline__ unsigned long long packkey(float v, int j) {
    unsigned u = __float_as_uint(v);
    u = (u & 0x80000000u) ? ~u : (u | 0x80000000u);   // total order on floats
    return ((unsigned long long)u << 32) | (unsigned)j;
}

// Blackwell packed fp32x2 FMA (one FFMA2 SASS op = 2 FMAs per issue slot)
__device__ __forceinline__ unsigned long long fma2(unsigned long long a,
                                                   unsigned long long b,
                                                   unsigned long long c) {
    unsigned long long d;
    asm("fma.rn.f32x2 %0, %1, %2, %3;" : "=l"(d) : "l"(a), "l"(b), "l"(c));
    return d;
}

__device__ __forceinline__ unsigned long long bcast2(float v) {
    unsigned long long d;
    asm("mov.b64 %0, {%1, %1};" : "=l"(d) : "r"(__float_as_uint(v)));
    return d;
}

// ---------------- phase 1: row L2-normalize + reset argmax state ---------------
__global__ void normalize_kernel(const float* __restrict__ x) {
    int row = blockIdx.x;
    int t   = threadIdx.x;                       // 256 threads, 1 float4 each
    float4 v = ((const float4*)(x + (size_t)row * DD))[t];
    float ss = v.x*v.x + v.y*v.y + v.z*v.z + v.w*v.w;
    #pragma unroll
    for (int o = 16; o > 0; o >>= 1) ss += __shfl_xor_sync(0xffffffffu, ss, o);
    __shared__ float ws[8];
    __shared__ float s_inv;
    if ((t & 31) == 0) ws[t >> 5] = ss;
    __syncthreads();
    if (t == 0) {
        float tot = 0.f;
        #pragma unroll
        for (int w = 0; w < 8; w++) tot += ws[w];
        float nrm = sqrtf(tot);
        s_inv = 1.0f / fmaxf(nrm, EPSF);
        g_best[row] = 0ULL;                      // reset per launch (graph replays!)
    }
    __syncthreads();
    float inv = s_inv;
    float4 o = make_float4(v.x*inv, v.y*inv, v.z*inv, v.w*inv);
    ((float4*)(g_xn + (size_t)row * DD))[t] = o;
}

// ---------------- phase 2: symmetric tiled GEMM + fused argmax -----------------
// Grid 128x128; only upper-triangular tile pairs (bi<=bj) do work.
__global__ __launch_bounds__(256, 2)
void simgemm_argmax_kernel() {
    int bi = blockIdx.y, bj = blockIdx.x;
    if (bj < bi) return;

    __shared__ float As[KCH][LDA];
    __shared__ float Bs[KCH][LDA];
    __shared__ unsigned long long rb[TILE];      // row-side candidates (tile I)
    __shared__ unsigned long long cb[TILE];      // col-side candidates (tile J)

    int t  = threadIdx.x;
    int tx = t & 15;            // j sub-tile 0..15
    int ty = t >> 4;            // i sub-tile 0..15
    if (t < TILE) { rb[t] = 0ULL; cb[t] = 0ULL; }

    // 4x8 accumulators, each ull packs rows (2*ii2, 2*ii2+1) for one jj
    unsigned long long acc[4][8] = {};

    const float* Arow = g_xn + (size_t)bi * TILE * DD;
    const float* Brow = g_xn + (size_t)bj * TILE * DD;

    for (int k0 = 0; k0 < DD; k0 += KCH) {
        __syncthreads();                         // also covers rb/cb init on iter 0
        #pragma unroll
        for (int q = 0; q < 4; q++) {
            int idx = q * 256 + t;               // 0..1023
            int row = idx >> 3;                  // 0..127
            int kq  = idx & 7;                   // float4 slot in k-chunk
            float4 a = *(const float4*)(Arow + (size_t)row * DD + k0 + kq * 4);
            float4 b = *(const float4*)(Brow + (size_t)row * DD + k0 + kq * 4);
            As[kq*4+0][row] = a.x; As[kq*4+1][row] = a.y;
            As[kq*4+2][row] = a.z; As[kq*4+3][row] = a.w;
            Bs[kq*4+0][row] = b.x; Bs[kq*4+1][row] = b.y;
            Bs[kq*4+2][row] = b.z; Bs[kq*4+3][row] = b.w;
        }
        __syncthreads();

        #pragma unroll
        for (int k = 0; k < KCH; k++) {
            const float* asrow = &As[k][ty * 8];
            const float* bsrow = &Bs[k][tx * 8];
            unsigned long long a2[4];
            #pragma unroll
            for (int ii2 = 0; ii2 < 4; ii2++)    // direct 8B pair loads (aligned)
                a2[ii2] = *(const unsigned long long*)(asrow + ii2 * 2);
            float4 b0 = *(const float4*)(bsrow);
            float4 b1 = *(const float4*)(bsrow + 4);
            unsigned long long b2[8];
            b2[0]=bcast2(b0.x); b2[1]=bcast2(b0.y); b2[2]=bcast2(b0.z); b2[3]=bcast2(b0.w);
            b2[4]=bcast2(b1.x); b2[5]=bcast2(b1.y); b2[6]=bcast2(b1.z); b2[7]=bcast2(b1.w);
            #pragma unroll
            for (int jj = 0; jj < 8; jj++)
                #pragma unroll
                for (int ii2 = 0; ii2 < 4; ii2++)
                    acc[ii2][jj] = fma2(a2[ii2], b2[jj], acc[ii2][jj]);
        }
    }

    // ---- epilogue: fused max/argmax ----
    int  ibase = bi * TILE + ty * 8;
    int  jbase = bj * TILE + tx * 8;
    bool diag  = (bi == bj);

    // row side: for each of my 8 i-rows, max over my 8 j-cols
    #pragma unroll
    for (int ii2 = 0; ii2 < 4; ii2++) {
        int ilo = ibase + 2*ii2, ihi = ilo + 1;
        float mlo = -1e30f, mhi = -1e30f;
        int   jlo = 0,      jhi = 0;
        #pragma unroll
        for (int jj = 0; jj < 8; jj++) {
            unsigned long long v = acc[ii2][jj];
            float clo = __uint_as_float((unsigned)v);
            float chi = __uint_as_float((unsigned)(v >> 32));
            int j = jbase + jj;
            if (diag && j == ilo) clo = -2.0f;   // mask self-similarity
            if (diag && j == ihi) chi = -2.0f;
            if (clo > mlo) { mlo = clo; jlo = j; }
            if (chi > mhi) { mhi = chi; jhi = j; }
        }
        atomicMax(&rb[ty*8 + 2*ii2],     packkey(mlo, jlo));
        atomicMax(&rb[ty*8 + 2*ii2 + 1], packkey(mhi, jhi));
    }
    // col side (symmetry): for each of my 8 j-cols, max over my 8 i-rows
    if (!diag) {
        #pragma unroll
        for (int jj = 0; jj < 8; jj++) {
            float m = -1e30f; int mi = 0;
            #pragma unroll
            for (int ii2 = 0; ii2 < 4; ii2++) {
                unsigned long long v = acc[ii2][jj];
                float clo = __uint_as_float((unsigned)v);
                float chi = __uint_as_float((unsigned)(v >> 32));
                if (clo > m) { m = clo; mi = ibase + 2*ii2; }
                if (chi > m) { m = chi; mi = ibase + 2*ii2 + 1; }
            }
            atomicMax(&cb[tx*8 + jj], packkey(m, mi));
        }
    }
    __syncthreads();
    if (t < TILE) {
        atomicMax(&g_best[bi * TILE + t], rb[t]);
        if (!diag) atomicMax(&g_best[bj * TILE + t], cb[t]);
    }
}

// ---------------- phase 3: exact distance + log per row ------------------------
__global__ void dist_log_kernel() {
    int i = blockIdx.x;
    int t = threadIdx.x;                         // 256 threads, 1 float4 each
    int j = (int)(unsigned)(g_best[i] & 0xffffffffULL);
    float4 a = ((const float4*)(g_xn + (size_t)i * DD))[t];
    float4 b = ((const float4*)(g_xn + (size_t)j * DD))[t];
    float dx = a.x - b.x + EPSF;
    float dy = a.y - b.y + EPSF;
    float dz = a.z - b.z + EPSF;
    float dw = a.w - b.w + EPSF;
    float ss = dx*dx + dy*dy + dz*dz + dw*dw;
    #pragma unroll
    for (int o = 16; o > 0; o >>= 1) ss += __shfl_xor_sync(0xffffffffu, ss, o);
    __shared__ float ws[8];
    if ((t & 31) == 0) ws[t >> 5] = ss;
    __syncthreads();
    if (t == 0) {
        float tot = 0.f;
        #pragma unroll
        for (int w = 0; w < 8; w++) tot += ws[w];
        g_logs[i] = logf(sqrtf(tot) + EPSF);
    }
}

// ---------------- phase 4: deterministic mean reduction ------------------------
__global__ void final_kernel(float* __restrict__ out) {
    int t = threadIdx.x;                         // 256 threads
    double s = 0.0;
    for (int q = t; q < NB; q += 256) s += (double)g_logs[q];
    __shared__ double sh[256];
    sh[t] = s;
    __syncthreads();
    for (int o = 128; o > 0; o >>= 1) {
        if (t < o) sh[t] += sh[t + o];
        __syncthreads();
    }
    if (t == 0) out[0] = (float)(-sh[0] / (double)NB);
}

// ---------------- launch -------------------------------------------------------
extern "C" void kernel_launch(void* const* d_in, const int* in_sizes, int n_in,
                              void* d_out, int out_size) {
    (void)in_sizes; (void)n_in; (void)out_size;
    const float* x = (const float*)d_in[0];

    normalize_kernel<<<NB, 256>>>(x);
    dim3 grid(NB / TILE, NB / TILE);             // 128 x 128, upper triangle active
    simgemm_argmax_kernel<<<grid, 256>>>();
    dist_log_kernel<<<NB, 256>>>();
    final_kernel<<<1, 256>>>((float*)d_out);
}

// round 11
// speedup vs baseline: 5.4343x; 5.4343x over previous
#include <cuda_runtime.h>
#include <cuda_bf16.h>
#include <cstdint>

#define NB    16384
#define DD    1024
#define EPSF  1e-8f
#define TILE  128
#define KCH   32                      // k elems per stage
#define NSTG  (DD / KCH)              // 32 stages
#define LDS_  40                      // smem row stride in bf16 (80 B, 16B-aligned)

// ---------------- device scratch (allocation-free rule) ------------------------
__device__ float               g_xn[(size_t)NB * DD];    // 64 MB fp32 normalized
__device__ __nv_bfloat16       g_xbf[(size_t)NB * DD];   // 32 MB bf16 normalized
__device__ unsigned long long  g_best[NB];
__device__ float               g_logs[NB];

// ---------------- helpers ------------------------------------------------------
__device__ __forceinline__ uint32_t smem_u32(const void* p) {
    uint32_t a;
    asm("{ .reg .u64 t; cvta.to.shared.u64 t, %1; cvt.u32.u64 %0, t; }" : "=r"(a) : "l"(p));
    return a;
}
__device__ __forceinline__ unsigned long long packkey(float v, int j) {
    unsigned u = __float_as_uint(v);
    u = (u & 0x80000000u) ? ~u : (u | 0x80000000u);   // total order on floats
    return ((unsigned long long)u << 32) | (unsigned)j;
}
__device__ __forceinline__ void cpasync16(uint32_t dst, const void* src) {
    asm volatile("cp.async.cg.shared.global [%0], [%1], 16;" :: "r"(dst), "l"(src) : "memory");
}
__device__ __forceinline__ void ldsm_x4(uint32_t* r, uint32_t addr) {
    asm volatile("ldmatrix.sync.aligned.m8n8.x4.shared.b16 {%0,%1,%2,%3}, [%4];"
                 : "=r"(r[0]), "=r"(r[1]), "=r"(r[2]), "=r"(r[3]) : "r"(addr));
}
__device__ __forceinline__ void mma16816(float* c, const uint32_t* a, uint32_t b0, uint32_t b1) {
    asm volatile("mma.sync.aligned.m16n8k16.row.col.f32.bf16.bf16.f32 "
                 "{%0,%1,%2,%3}, {%4,%5,%6,%7}, {%8,%9}, {%0,%1,%2,%3};"
                 : "+f"(c[0]), "+f"(c[1]), "+f"(c[2]), "+f"(c[3])
                 : "r"(a[0]), "r"(a[1]), "r"(a[2]), "r"(a[3]), "r"(b0), "r"(b1));
}

// ---------------- phase 1: normalize -> fp32 + bf16, reset g_best --------------
__global__ void normalize_kernel(const float* __restrict__ x) {
    int row = blockIdx.x;
    int t   = threadIdx.x;                       // 256 threads, 1 float4 each
    float4 v = ((const float4*)(x + (size_t)row * DD))[t];
    float ss = v.x*v.x + v.y*v.y + v.z*v.z + v.w*v.w;
    #pragma unroll
    for (int o = 16; o > 0; o >>= 1) ss += __shfl_xor_sync(0xffffffffu, ss, o);
    __shared__ float ws[8];
    __shared__ float s_inv;
    if ((t & 31) == 0) ws[t >> 5] = ss;
    __syncthreads();
    if (t == 0) {
        float tot = 0.f;
        #pragma unroll
        for (int w = 0; w < 8; w++) tot += ws[w];
        s_inv = 1.0f / fmaxf(sqrtf(tot), EPSF);
        g_best[row] = 0ULL;                      // per-replay reset
    }
    __syncthreads();
    float inv = s_inv;
    float4 o = make_float4(v.x*inv, v.y*inv, v.z*inv, v.w*inv);
    ((float4*)(g_xn + (size_t)row * DD))[t] = o;
    __nv_bfloat162 b01 = __floats2bfloat162_rn(o.x, o.y);
    __nv_bfloat162 b23 = __floats2bfloat162_rn(o.z, o.w);
    uint2 pk;
    pk.x = *(uint32_t*)&b01; pk.y = *(uint32_t*)&b23;
    ((uint2*)(g_xbf + (size_t)row * DD))[t] = pk;
}

// ---------------- phase 2: HMMA GEMM (triangular) + fused argmax ---------------
// 8 warps as 2x4: warp covers rows [wr*64,+64) x cols [wc*32,+32) of 128x128 tile.
__global__ __launch_bounds__(256, 2)
void simgemm_mma_kernel() {
    __shared__ __nv_bfloat16       As[2][TILE * LDS_];
    __shared__ __nv_bfloat16       Bs[2][TILE * LDS_];
    __shared__ unsigned long long  rb[TILE];
    __shared__ unsigned long long  cb[TILE];

    const int bi = blockIdx.y, bj = blockIdx.x;
    if (bj < bi) return;
    const bool diag = (bi == bj);

    const int t   = threadIdx.x;
    const int wid = t >> 5, lid = t & 31;
    const int wr  = wid >> 2, wc = wid & 3;      // 2 x 4 warp grid

    if (t < TILE) { rb[t] = 0ULL; cb[t] = 0ULL; }

    const uint32_t Ab[2] = { smem_u32(As[0]), smem_u32(As[1]) };
    const uint32_t Bb[2] = { smem_u32(Bs[0]), smem_u32(Bs[1]) };

    // per-lane ldmatrix base offsets (bytes)
    const int r8 = lid & 7, g4 = lid >> 3;
    // A x4: tiles (rows+0,k0)(rows+8,k0)(rows+0,k8)(rows+8,k8)
    const uint32_t aoff = (uint32_t)((wr * 64 + r8 + (g4 & 1) * 8) * (LDS_ * 2) + (g4 >> 1) * 16);
    // B x4: tiles (n+0..7,k0)(n+0..7,k8)(n+8..15,k0)(n+8..15,k8)
    const uint32_t boff = (uint32_t)((wc * 32 + (g4 >> 1) * 8 + r8) * (LDS_ * 2) + (g4 & 1) * 16);

    float acc[4][4][4];                          // [mi2][ni2][frag]
    #pragma unroll
    for (int i = 0; i < 4; i++)
        #pragma unroll
        for (int j = 0; j < 4; j++)
            #pragma unroll
            for (int r = 0; r < 4; r++) acc[i][j][r] = 0.f;

    const char* xb = (const char*)g_xbf;         // row stride 2048 B
    const size_t arow0 = (size_t)bi * TILE, brow0 = (size_t)bj * TILE;

    // chunk map: q<512 -> A row q>>2 chunk q&3 ; else B
    // stage s reads bytes [s*64, s*64+64) of each row
    auto issue = [&](int s, int p) {
        #pragma unroll
        for (int i = 0; i < 4; i++) {
            int q = t + i * 256;
            int isB = q >> 9;                    // 0: A, 1: B
            int qq = q & 511;
            int r = qq >> 2, c = qq & 3;
            uint32_t dst = (isB ? Bb[p] : Ab[p]) + (uint32_t)(r * (LDS_ * 2) + c * 16);
            const char* src = xb + ((isB ? brow0 : arow0) + r) * 2048 + s * 64 + c * 16;
            cpasync16(dst, src);
        }
        asm volatile("cp.async.commit_group;" ::: "memory");
    };

    issue(0, 0);
    for (int s = 0; s < NSTG; s++) {
        int p = s & 1;
        if (s + 1 < NSTG) {
            issue(s + 1, (s + 1) & 1);
            asm volatile("cp.async.wait_group 1;" ::: "memory");
        } else {
            asm volatile("cp.async.wait_group 0;" ::: "memory");
        }
        __syncthreads();

        #pragma unroll
        for (int kf = 0; kf < 2; kf++) {         // two k16 frags per stage
            uint32_t a[4][4];
            #pragma unroll
            for (int mi2 = 0; mi2 < 4; mi2++)
                ldsm_x4(a[mi2], Ab[p] + aoff + (uint32_t)(mi2 * 16 * (LDS_ * 2) + kf * 32));
            #pragma unroll
            for (int np = 0; np < 2; np++) {
                uint32_t b[4];
                ldsm_x4(b, Bb[p] + boff + (uint32_t)(np * 16 * (LDS_ * 2) + kf * 32));
                #pragma unroll
                for (int mi2 = 0; mi2 < 4; mi2++) {
                    mma16816(acc[mi2][np * 2 + 0], a[mi2], b[0], b[1]);
                    mma16816(acc[mi2][np * 2 + 1], a[mi2], b[2], b[3]);
                }
            }
        }
        __syncthreads();                         // protect buf p before reissue
    }

    // ---- epilogue: row-side + col-side argmax over the 128x128 tile ----
    const int rloc0 = wr * 64 + (lid >> 2);      // + mi2*16 + rh*8
    const int cloc0 = wc * 32 + (lid & 3) * 2;   // + ni2*8 + c01
    const int ibase = bi * TILE, jbase = bj * TILE;

    // row side: 8 rows per thread, max over 8 cols held
    #pragma unroll
    for (int mi2 = 0; mi2 < 4; mi2++)
        #pragma unroll
        for (int rh = 0; rh < 2; rh++) {
            int rloc = rloc0 + mi2 * 16 + rh * 8;
            int rowg = ibase + rloc;
            float m = -2.0f; int mj = 0;
            #pragma unroll
            for (int ni2 = 0; ni2 < 4; ni2++)
                #pragma unroll
                for (int c01 = 0; c01 < 2; c01++) {
                    int colg = jbase + cloc0 + ni2 * 8 + c01;
                    float v = acc[mi2][ni2][rh * 2 + c01];
                    if (diag && colg == rowg) v = -2.0f;
                    if (v > m) { m = v; mj = colg; }
                }
            atomicMax(&rb[rloc], packkey(m, mj));
        }
    // col side: 8 cols per thread, max over 8 rows held
    if (!diag) {
        #pragma unroll
        for (int ni2 = 0; ni2 < 4; ni2++)
            #pragma unroll
            for (int c01 = 0; c01 < 2; c01++) {
                int cloc = cloc0 + ni2 * 8 + c01;
                float m = -2.0f; int mi = 0;
                #pragma unroll
                for (int mi2 = 0; mi2 < 4; mi2++)
                    #pragma unroll
                    for (int rh = 0; rh < 2; rh++) {
                        float v = acc[mi2][ni2][rh * 2 + c01];
                        int rowg = ibase + rloc0 + mi2 * 16 + rh * 8;
                        if (v > m) { m = v; mi = rowg; }
                    }
                atomicMax(&cb[cloc], packkey(m, mi));
            }
    }
    __syncthreads();
    if (t < TILE) {
        atomicMax(&g_best[ibase + t], rb[t]);
        if (!diag) atomicMax(&g_best[jbase + t], cb[t]);
    }
}

// ---------------- phase 3: exact fp32 distance + log ---------------------------
__global__ void dist_log_kernel() {
    int i = blockIdx.x;
    int t = threadIdx.x;
    int j = (int)(unsigned)(g_best[i] & 0xffffffffULL);
    float4 a = ((const float4*)(g_xn + (size_t)i * DD))[t];
    float4 b = ((const float4*)(g_xn + (size_t)j * DD))[t];
    float dx = a.x - b.x + EPSF, dy = a.y - b.y + EPSF;
    float dz = a.z - b.z + EPSF, dw = a.w - b.w + EPSF;
    float ss = dx*dx + dy*dy + dz*dz + dw*dw;
    #pragma unroll
    for (int o = 16; o > 0; o >>= 1) ss += __shfl_xor_sync(0xffffffffu, ss, o);
    __shared__ float ws[8];
    if ((t & 31) == 0) ws[t >> 5] = ss;
    __syncthreads();
    if (t == 0) {
        float tot = 0.f;
        #pragma unroll
        for (int w = 0; w < 8; w++) tot += ws[w];
        g_logs[i] = logf(sqrtf(tot) + EPSF);
    }
}

// ---------------- phase 4: deterministic mean ----------------------------------
__global__ void final_kernel(float* __restrict__ out) {
    int t = threadIdx.x;
    double s = 0.0;
    for (int q = t; q < NB; q += 256) s += (double)g_logs[q];
    __shared__ double sh[256];
    sh[t] = s;
    __syncthreads();
    for (int o = 128; o > 0; o >>= 1) {
        if (t < o) sh[t] += sh[t + o];
        __syncthreads();
    }
    if (t == 0) out[0] = (float)(-sh[0] / (double)NB);
}

// ---------------- launch -------------------------------------------------------
extern "C" void kernel_launch(void* const* d_in, const int* in_sizes, int n_in,
                              void* d_out, int out_size) {
    (void)in_sizes; (void)n_in; (void)out_size;
    const float* x = (const float*)d_in[0];

    normalize_kernel<<<NB, 256>>>(x);
    dim3 grid(NB / TILE, NB / TILE);             // 128 x 128, upper triangle active
    simgemm_mma_kernel<<<grid, 256>>>();
    dist_log_kernel<<<NB, 256>>>();
    final_kernel<<<1, 256>>>((float*)d_out);
}